// round 17
// baseline (speedup 1.0000x reference)
#include <cuda_runtime.h>
#include <cstdint>

// out[i, :] = embedding[index[i], :],  U=1M rows, D=64 f32 (256B/row), N=2M.
// FINAL kernel — best measured configuration (149.6us twice-confirmed,
// ~82% DRAM cycles, ~6.5TB/s effective):
//   16 threads per row, one float4 each (row = exactly 2 full 128B lines),
//   UNROLL=8 front-batched independent gathers (256B in flight per thread),
//   exact straight-line grid cover (no loop in the hot path).
//   emb : ld.global.cg  (L2-only; random lines, no L1 reuse)
//   idx : __ldg         (L1; 16-lane broadcast of the same word)
//   out : __stcs        (evict-first streaming write)
// Plateau characterization: ~940MB irreducible traffic (512MB compulsory
// write + ~430MB reads; table is 2x L2 so duplicate dedup is capacity-capped,
// insensitive to eviction policy) at the memory controller's ~82% efficiency
// for mixed random-256B-read + streaming-write. All structural levers
// (MLP depth, load width, cache ops, write policy, 3 partitioning designs,
// block size, index staging, tile mapping) measured flat or worse.

static constexpr int UNROLL = 8;

__device__ __forceinline__ float4 ldcg4(const float4* p) {
    float4 v;
    asm("ld.global.cg.v4.f32 {%0,%1,%2,%3}, [%4];"
        : "=f"(v.x), "=f"(v.y), "=f"(v.z), "=f"(v.w)
        : "l"(p));
    return v;
}

__global__ __launch_bounds__(256) void gather_kernel(
    const float4* __restrict__ emb,   // [U * 16] float4
    const int*    __restrict__ idx,   // [N]
    float4*       __restrict__ out,   // [N * 16] float4
    unsigned n_vec)                   // N * 16 = 2^25
{
    const unsigned stride = gridDim.x * blockDim.x;          // n_vec / 8
    const unsigned g0 = blockIdx.x * blockDim.x + threadIdx.x;

    if (g0 + (UNROLL - 1) * stride < n_vec) {
        // Exact-cover fast path: straight-line 8 independent gathers.
        unsigned gg[UNROLL];
        int      src[UNROLL];
#pragma unroll
        for (int u = 0; u < UNROLL; u++) {
            gg[u] = g0 + u * stride;
            src[u] = __ldg(&idx[gg[u] >> 4]);
        }
        float4 v[UNROLL];
#pragma unroll
        for (int u = 0; u < UNROLL; u++) {
            unsigned seg = gg[u] & 15u;
            v[u] = ldcg4(&emb[((int64_t)src[u] << 4) + seg]);
        }
#pragma unroll
        for (int u = 0; u < UNROLL; u++) {
            __stcs(&out[gg[u]], v[u]);
        }
    } else {
        // Generic tail (only if sizes aren't the expected exact fit).
        for (unsigned g = g0; g < n_vec; g += stride) {
            int src = __ldg(&idx[g >> 4]);
            unsigned seg = g & 15u;
            float4 v = ldcg4(&emb[((int64_t)src << 4) + seg]);
            __stcs(&out[g], v);
        }
    }
}

extern "C" void kernel_launch(void* const* d_in, const int* in_sizes, int n_in,
                              void* d_out, int out_size) {
    const float4* emb = (const float4*)d_in[0];  // embedding [U, 64] f32
    const int*    idx = (const int*)d_in[1];     // index [N] i32
    float4*       out = (float4*)d_out;

    int64_t n = in_sizes[1];                     // N = 2097152
    unsigned n_vec = (unsigned)(n * 16);         // 33,554,432

    const int threads = 256;
    unsigned blocks = (n_vec + threads * UNROLL - 1) / (threads * UNROLL); // 16384
    gather_kernel<<<blocks, threads>>>(emb, idx, out, n_vec);
}